// round 1
// baseline (speedup 1.0000x reference)
#include <cuda_runtime.h>
#include <cstdint>

#define T_TOK 8192
#define DIM   1024
#define NEXP  8
#define KTOP  2
#define NPAIR (T_TOK * KTOP)

#define BM 128
#define BN 128
#define BK 16

// ---- scratch (static device globals: allocation-free per harness rules) ----
__device__ int   g_off[NEXP + 1];
__device__ int   g_pairs[NPAIR];
__device__ float g_H[(size_t)NPAIR * DIM];   // 64 MB intermediate (relu(x@W1^T))

// ---------------------------------------------------------------------------
// Routing: bucket the 16384 (token,expert) pairs by expert.
// Single block; shared-atomic histogram + prefix + scatter.
// Order within a bucket is nondeterministic, but every pair's GEMM result is
// independent of its row slot, and the final combine is 2 commutative float
// adds per element -> bitwise-deterministic output.
// ---------------------------------------------------------------------------
__global__ void route_kernel(const int* __restrict__ idx) {
    __shared__ int hist[NEXP];
    __shared__ int cur[NEXP];
    int tid = threadIdx.x;
    if (tid < NEXP) hist[tid] = 0;
    __syncthreads();
    for (int p = tid; p < NPAIR; p += blockDim.x)
        atomicAdd(&hist[idx[p]], 1);
    __syncthreads();
    if (tid == 0) {
        int acc = 0;
        for (int e = 0; e < NEXP; e++) {
            g_off[e] = acc;
            cur[e]   = acc;
            acc += hist[e];
        }
        g_off[NEXP] = acc;
    }
    __syncthreads();
    for (int p = tid; p < NPAIR; p += blockDim.x) {
        int e = idx[p];
        int slot = atomicAdd(&cur[e], 1);
        g_pairs[slot] = p;
    }
}

// ---------------------------------------------------------------------------
// Grouped GEMM, 128x128x16 tile, 256 threads, 8x8 per thread.
// C[i,j] = sum_k A[i,k] * W[e][j,k]   (both operands k-contiguous)
// FC1: A = gathered x rows          -> g_H = relu(C)
// FC2: A = g_H rows                 -> out[t] += w_p * relu(C)   (atomicAdd)
// Inner product uses packed fma.rn.f32x2 (2 MACs/inst) — B pairs come free
// from the float4 smem layout; A lane-duplicated with one mov.b64 per i.
// ---------------------------------------------------------------------------
template <bool FC2>
__global__ __launch_bounds__(256)
void moe_gemm(const float* __restrict__ X,
              const float* __restrict__ W,    // [E, D, D] row-major, k fastest
              const float* __restrict__ fw,   // pair weights (FC2)
              float* __restrict__ out)        // d_out (FC2)
{
    const int e      = blockIdx.z;
    const int rowBeg = g_off[e];
    const int rowEnd = g_off[e + 1];
    const int row0   = rowBeg + blockIdx.x * BM;
    if (row0 >= rowEnd) return;
    const int n0 = blockIdx.y * BN;

    __shared__ float As[BK][BM + 4];
    __shared__ float Bs[BK][BN + 4];

    const int tid = threadIdx.x;
    const int tx  = tid & 15;        // output col group
    const int ty  = tid >> 4;        // output row group

    // global->smem loader assignment: 2 rows per thread, one float4 along k
    const int ar1 = tid >> 2;
    const int ar2 = ar1 + 64;
    const int kq  = (tid & 3) * 4;

    const bool v1 = (row0 + ar1) < rowEnd;
    const bool v2 = (row0 + ar2) < rowEnd;

    const float* aptr1;
    const float* aptr2;
    if constexpr (FC2) {
        aptr1 = g_H + (size_t)(row0 + ar1) * DIM + kq;
        aptr2 = g_H + (size_t)(row0 + ar2) * DIM + kq;
    } else {
        int t1 = v1 ? (g_pairs[row0 + ar1] >> 1) : 0;
        int t2 = v2 ? (g_pairs[row0 + ar2] >> 1) : 0;
        aptr1 = X + (size_t)t1 * DIM + kq;
        aptr2 = X + (size_t)t2 * DIM + kq;
    }
    const float* bptr1 = W + ((size_t)e * DIM + n0 + ar1) * DIM + kq;
    const float* bptr2 = W + ((size_t)e * DIM + n0 + ar2) * DIM + kq;

    unsigned long long acc[8][4];
#pragma unroll
    for (int i = 0; i < 8; i++)
#pragma unroll
        for (int j = 0; j < 4; j++) acc[i][j] = 0ULL;   // (+0.f, +0.f)

    for (int k0 = 0; k0 < DIM; k0 += BK) {
        const float4 z4  = make_float4(0.f, 0.f, 0.f, 0.f);
        float4 av1 = v1 ? *(const float4*)(aptr1 + k0) : z4;
        float4 av2 = v2 ? *(const float4*)(aptr2 + k0) : z4;
        float4 bv1 = *(const float4*)(bptr1 + k0);
        float4 bv2 = *(const float4*)(bptr2 + k0);

        __syncthreads();   // previous tile fully consumed
        As[kq + 0][ar1] = av1.x; As[kq + 1][ar1] = av1.y;
        As[kq + 2][ar1] = av1.z; As[kq + 3][ar1] = av1.w;
        As[kq + 0][ar2] = av2.x; As[kq + 1][ar2] = av2.y;
        As[kq + 2][ar2] = av2.z; As[kq + 3][ar2] = av2.w;
        Bs[kq + 0][ar1] = bv1.x; Bs[kq + 1][ar1] = bv1.y;
        Bs[kq + 2][ar1] = bv1.z; Bs[kq + 3][ar1] = bv1.w;
        Bs[kq + 0][ar2] = bv2.x; Bs[kq + 1][ar2] = bv2.y;
        Bs[kq + 2][ar2] = bv2.z; Bs[kq + 3][ar2] = bv2.w;
        __syncthreads();

#pragma unroll
        for (int kk = 0; kk < BK; kk++) {
            const float4* arow = (const float4*)&As[kk][ty * 8];
            float4 a0 = arow[0];
            float4 a1 = arow[1];
            ulonglong2 bA = *(const ulonglong2*)&Bs[kk][tx * 8];
            ulonglong2 bB = *(const ulonglong2*)&Bs[kk][tx * 8 + 4];
            unsigned long long bp0 = bA.x, bp1 = bA.y, bp2 = bB.x, bp3 = bB.y;

            float av[8] = {a0.x, a0.y, a0.z, a0.w, a1.x, a1.y, a1.z, a1.w};
#pragma unroll
            for (int i = 0; i < 8; i++) {
                unsigned long long ap;
                asm("mov.b64 %0, {%1, %1};"
                    : "=l"(ap) : "r"(__float_as_uint(av[i])));
                asm("fma.rn.f32x2 %0, %1, %2, %0;" : "+l"(acc[i][0]) : "l"(ap), "l"(bp0));
                asm("fma.rn.f32x2 %0, %1, %2, %0;" : "+l"(acc[i][1]) : "l"(ap), "l"(bp1));
                asm("fma.rn.f32x2 %0, %1, %2, %0;" : "+l"(acc[i][2]) : "l"(ap), "l"(bp2));
                asm("fma.rn.f32x2 %0, %1, %2, %0;" : "+l"(acc[i][3]) : "l"(ap), "l"(bp3));
            }
        }
    }

    // epilogue
#pragma unroll
    for (int i = 0; i < 8; i++) {
        int s = row0 + ty * 8 + i;
        if (s >= rowEnd) continue;
        float c[8];
#pragma unroll
        for (int j2 = 0; j2 < 4; j2++) {
            c[2 * j2 + 0] = __uint_as_float((unsigned)(acc[i][j2] & 0xffffffffULL));
            c[2 * j2 + 1] = __uint_as_float((unsigned)(acc[i][j2] >> 32));
        }
        if constexpr (!FC2) {
            float* hp = g_H + (size_t)s * DIM + n0 + tx * 8;
            float4 o0 = make_float4(fmaxf(c[0], 0.f), fmaxf(c[1], 0.f),
                                    fmaxf(c[2], 0.f), fmaxf(c[3], 0.f));
            float4 o1 = make_float4(fmaxf(c[4], 0.f), fmaxf(c[5], 0.f),
                                    fmaxf(c[6], 0.f), fmaxf(c[7], 0.f));
            ((float4*)hp)[0] = o0;
            ((float4*)hp)[1] = o1;
        } else {
            int   p = g_pairs[s];
            int   t = p >> 1;          // K = 2
            float w = fw[p];
            float* op = out + (size_t)t * DIM + n0 + tx * 8;
#pragma unroll
            for (int j = 0; j < 8; j++)
                atomicAdd(op + j, fmaxf(c[j], 0.f) * w);
        }
    }
}

// ---------------------------------------------------------------------------
// inputs (metadata order): x[T*D] f32, flat_expert_indices[T*K] i32,
//                          flat_expert_weights[T*K] f32, W1[E*D*D], W2[E*D*D]
// output: [T*D] f32
// ---------------------------------------------------------------------------
extern "C" void kernel_launch(void* const* d_in, const int* in_sizes, int n_in,
                              void* d_out, int out_size) {
    const float* x   = (const float*)d_in[0];
    const int*   fi  = (const int*)d_in[1];
    const float* fwt = (const float*)d_in[2];
    const float* W1  = (const float*)d_in[3];
    const float* W2  = (const float*)d_in[4];
    float* out = (float*)d_out;

    cudaMemsetAsync(out, 0, (size_t)T_TOK * DIM * sizeof(float));

    route_kernel<<<1, 256>>>(fi);

    dim3 grid(NPAIR / BM, DIM / BN, NEXP);   // worst-case m-tiles; early-exit
    moe_gemm<false><<<grid, 256>>>(x, W1, nullptr, nullptr);
    moe_gemm<true ><<<grid, 256>>>(x, W2, fwt, out);
}

// round 3
// speedup vs baseline: 1.6000x; 1.6000x over previous
#include <cuda_runtime.h>
#include <cstdint>

#define T_TOK 8192
#define DIM   1024
#define NEXP  8
#define NPAIR (T_TOK * 2)

#define BM 128
#define BN 128
#define BK 32
#define NC (DIM / BK)            // 32 k-chunks
#define STAGES 4
#define ASTRIDE 36               // padded floats per smem row (conflict-free frags)
#define TILE_F  (BM * ASTRIDE)   // 4608 floats
#define STAGE_F (2 * TILE_F)     // A + B
#define SMEM_BYTES (STAGES * STAGE_F * 4)   // 147456
#define MAXITEMS 1536
#define WELEM (NEXP * DIM * DIM) // 8M floats per weight tensor

// ---- device scratch (allocation-free) ----
__device__ int   g_off[NEXP + 1];
__device__ int   g_pairs[NPAIR];
__device__ int   g_nwork;
__device__ int   g_items[MAXITEMS];
__device__ float g_W[2 * WELEM];             // tf32-rounded W1 | W2 (128 MB)
__device__ float g_H[(size_t)NPAIR * DIM];   // relu(x@W1^T), tf32-rounded, by slot
__device__ float g_Y[(size_t)NPAIR * DIM];   // w*relu(h@W2^T), by ORIGINAL pair id

// ---- helpers ----
__device__ __forceinline__ uint32_t smem_u32(const void* p) {
    uint32_t a;
    asm("{ .reg .u64 t; cvta.to.shared.u64 t, %1; cvt.u32.u64 %0, t; }"
        : "=r"(a) : "l"(p));
    return a;
}
#define CP16(dst, src) \
    asm volatile("cp.async.cg.shared.global [%0], [%1], 16;" :: "r"(dst), "l"(src))
#define CP_COMMIT() asm volatile("cp.async.commit_group;" ::: "memory")
#define CP_WAIT(n)  asm volatile("cp.async.wait_group %0;" :: "n"(n) : "memory")

__device__ __forceinline__ uint32_t to_tf32(float f) {
    uint32_t o;
    asm("cvt.rna.tf32.f32 %0, %1;" : "=r"(o) : "f"(f));
    return o;
}
__device__ __forceinline__ void mma_tf32(float* c, const uint32_t* a,
                                         const uint32_t* b) {
    asm volatile(
        "mma.sync.aligned.m16n8k8.row.col.f32.tf32.tf32.f32 "
        "{%0,%1,%2,%3}, {%4,%5,%6,%7}, {%8,%9}, {%0,%1,%2,%3};"
        : "+f"(c[0]), "+f"(c[1]), "+f"(c[2]), "+f"(c[3])
        : "r"(a[0]), "r"(a[1]), "r"(a[2]), "r"(a[3]), "r"(b[0]), "r"(b[1]));
}

// ---------------------------------------------------------------------------
// Prep: blocks [0,2048) round W1|W2 to tf32 into g_W; block 2048 does routing
// and builds the tile work list. 256 threads everywhere.
// ---------------------------------------------------------------------------
__global__ void prep_kernel(const int* __restrict__ idx,
                            const float* __restrict__ W1,
                            const float* __restrict__ W2) {
    const int tid = threadIdx.x;
    if (blockIdx.x < 2048) {
        const int b = blockIdx.x;
        const float4* src = (const float4*)((b < 1024) ? W1 : W2);
        const int bo = (b & 1023) * 4096;               // float4 index
        float4* dst = (float4*)g_W + (b < 1024 ? 0 : WELEM / 4) + bo;
        src += bo;
#pragma unroll
        for (int j = 0; j < 16; j++) {
            float4 v = src[tid + j * 256];
            float4 o;
            o.x = __uint_as_float(to_tf32(v.x));
            o.y = __uint_as_float(to_tf32(v.y));
            o.z = __uint_as_float(to_tf32(v.z));
            o.w = __uint_as_float(to_tf32(v.w));
            dst[tid + j * 256] = o;
        }
        return;
    }
    // ---- routing block ----
    __shared__ int hist[NEXP];
    __shared__ int cur[NEXP];
    if (tid < NEXP) hist[tid] = 0;
    __syncthreads();
    for (int p = tid; p < NPAIR; p += 256) atomicAdd(&hist[idx[p]], 1);
    __syncthreads();
    if (tid == 0) {
        int acc = 0, nw = 0;
        for (int e = 0; e < NEXP; e++) {
            g_off[e] = acc;
            cur[e]   = acc;
            int mt = (hist[e] + BM - 1) / BM;
            for (int m = 0; m < mt; m++)
                for (int n = 0; n < DIM / BN; n++)
                    g_items[nw++] = e | (m << 4) | (n << 12);
            acc += hist[e];
        }
        g_off[NEXP] = acc;
        g_nwork = nw;
    }
    __syncthreads();
    for (int p = tid; p < NPAIR; p += 256)
        g_pairs[atomicAdd(&cur[idx[p]], 1)] = p;
}

// ---------------------------------------------------------------------------
// Persistent grouped GEMM, mma.sync m16n8k8 tf32.
// C[i,j] = sum_k A[i,k] * W[e][j,k]
// FC1: A = gathered x rows (cvt in-loop) -> g_H[slot] = tf32(relu(C))
// FC2: A = g_H rows (pre-rounded)        -> g_Y[pair] = fw*relu(C)
// ---------------------------------------------------------------------------
template <bool FC2>
__global__ __launch_bounds__(256, 1)
void moe_gemm(const float* __restrict__ X, const float* __restrict__ fw)
{
    extern __shared__ float smem[];
    const uint32_t sbase = smem_u32(smem);
    const int tid  = threadIdx.x;
    const int wid  = tid >> 5;
    const int lane = tid & 31;
    const int g = lane >> 2;          // groupID
    const int t = lane & 3;           // threadID_in_group
    const int wm = wid & 3;           // warp m index (4)
    const int wn = wid >> 2;          // warp n index (2)

    // loader geometry: row = tid&127, 4 consecutive float4 along k
    const int lrow = tid & 127;
    const int lq   = (tid >> 7) * 4;  // float4 index within 32-float row
    const uint32_t dstA0 = (uint32_t)lrow * (ASTRIDE * 4) + (uint32_t)lq * 16;

    const float* Wbase = g_W + (FC2 ? WELEM : 0);
    const int nwork = g_nwork;

    for (int w = blockIdx.x; w < nwork; w += gridDim.x) {
        const int item = g_items[w];
        const int e  = item & 15;
        const int mt = (item >> 4) & 255;
        const int nt = (item >> 12) & 15;
        const int rowEnd = g_off[e + 1];
        const int row0   = g_off[e] + mt * BM;
        const int n0     = nt * BN;

        const int s = min(row0 + lrow, rowEnd - 1);
        const float* aPtr;
        if constexpr (FC2) aPtr = g_H + (size_t)s * DIM;
        else               aPtr = X + (size_t)(g_pairs[s] >> 1) * DIM;
        const float* bPtr = Wbase + ((size_t)e * DIM + n0 + lrow) * DIM;

        auto issue = [&](int c) {
            uint32_t sb = sbase + (uint32_t)(c & (STAGES - 1)) * (STAGE_F * 4);
            const float* a = aPtr + c * BK + lq * 4;
            const float* b = bPtr + c * BK + lq * 4;
#pragma unroll
            for (int j = 0; j < 4; j++) {
                CP16(sb + dstA0 + j * 16, a + j * 4);
                CP16(sb + TILE_F * 4 + dstA0 + j * 16, b + j * 4);
            }
            CP_COMMIT();
        };

        float acc[2][8][4];
#pragma unroll
        for (int mi = 0; mi < 2; mi++)
#pragma unroll
            for (int nj = 0; nj < 8; nj++)
#pragma unroll
                for (int q = 0; q < 4; q++) acc[mi][nj][q] = 0.f;

        issue(0); issue(1); issue(2);

        for (int c = 0; c < NC; c++) {
            if (c + 3 < NC) issue(c + 3);
            if      (c <  NC - 3) CP_WAIT(3);
            else if (c == NC - 3) CP_WAIT(2);
            else if (c == NC - 2) CP_WAIT(1);
            else                  CP_WAIT(0);
            __syncthreads();

            const float* As = smem + (c & (STAGES - 1)) * STAGE_F;
            const float* Bs = As + TILE_F;
#pragma unroll
            for (int ks = 0; ks < 4; ks++) {
                const int kc = ks * 8;
                uint32_t a[2][4];
#pragma unroll
                for (int mi = 0; mi < 2; mi++) {
                    const int r = wm * 32 + mi * 16 + g;
                    float f0 = As[r * ASTRIDE + kc + t];
                    float f1 = As[(r + 8) * ASTRIDE + kc + t];
                    float f2 = As[r * ASTRIDE + kc + t + 4];
                    float f3 = As[(r + 8) * ASTRIDE + kc + t + 4];
                    if constexpr (FC2) {
                        a[mi][0] = __float_as_uint(f0);
                        a[mi][1] = __float_as_uint(f1);
                        a[mi][2] = __float_as_uint(f2);
                        a[mi][3] = __float_as_uint(f3);
                    } else {
                        a[mi][0] = to_tf32(f0);
                        a[mi][1] = to_tf32(f1);
                        a[mi][2] = to_tf32(f2);
                        a[mi][3] = to_tf32(f3);
                    }
                }
                uint32_t b[8][2];
#pragma unroll
                for (int nj = 0; nj < 8; nj++) {
                    const int n = wn * 64 + nj * 8 + g;
                    b[nj][0] = __float_as_uint(Bs[n * ASTRIDE + kc + t]);
                    b[nj][1] = __float_as_uint(Bs[n * ASTRIDE + kc + t + 4]);
                }
#pragma unroll
                for (int mi = 0; mi < 2; mi++)
#pragma unroll
                    for (int nj = 0; nj < 8; nj++)
                        mma_tf32(acc[mi][nj], a[mi], b[nj]);
            }
            __syncthreads();
        }

        // epilogue: each thread owns rows wm*32+mi*16+h*8+g, cols wn*64+nj*8+2t
#pragma unroll
        for (int mi = 0; mi < 2; mi++)
#pragma unroll
            for (int h = 0; h < 2; h++) {
                const int sr = row0 + wm * 32 + mi * 16 + h * 8 + g;
                if (sr >= rowEnd) continue;
                float wsc = 1.0f;
                float* dst;
                if constexpr (FC2) {
                    const int p = g_pairs[sr];
                    wsc = fw[p];
                    dst = g_Y + (size_t)p * DIM + n0;
                } else {
                    dst = g_H + (size_t)sr * DIM + n0;
                }
#pragma unroll
                for (int nj = 0; nj < 8; nj++) {
                    const int col = wn * 64 + nj * 8 + 2 * t;
                    float v0 = fmaxf(acc[mi][nj][h * 2 + 0], 0.f);
                    float v1 = fmaxf(acc[mi][nj][h * 2 + 1], 0.f);
                    float2 o;
                    if constexpr (FC2) {
                        o.x = v0 * wsc; o.y = v1 * wsc;
                    } else {   // round H to tf32 so FC2 can skip in-loop cvt
                        o.x = __uint_as_float(to_tf32(v0));
                        o.y = __uint_as_float(to_tf32(v1));
                    }
                    *(float2*)(dst + col) = o;
                }
            }
        __syncthreads();   // protect smem ring before next tile's prologue
    }
}

// ---------------------------------------------------------------------------
// Combine: out[t] = Y[2t] + Y[2t+1]  (K = 2), coalesced, deterministic.
// ---------------------------------------------------------------------------
__global__ void combine_kernel(float* __restrict__ out) {
    const int i = blockIdx.x * blockDim.x + threadIdx.x;   // T*D/4 elements
    const float4* Y = (const float4*)g_Y;
    const int tk = i >> 8;          // token (256 float4 per row)
    const int rem = i & 255;
    float4 a = Y[(size_t)tk * 512 + rem];
    float4 b = Y[(size_t)tk * 512 + 256 + rem];
    float4 o;
    o.x = a.x + b.x; o.y = a.y + b.y; o.z = a.z + b.z; o.w = a.w + b.w;
    ((float4*)out)[i] = o;
}

// ---------------------------------------------------------------------------
extern "C" void kernel_launch(void* const* d_in, const int* in_sizes, int n_in,
                              void* d_out, int out_size) {
    const float* x   = (const float*)d_in[0];
    const int*   fi  = (const int*)d_in[1];
    const float* fwt = (const float*)d_in[2];
    const float* W1  = (const float*)d_in[3];
    const float* W2  = (const float*)d_in[4];
    float* out = (float*)d_out;

    cudaFuncSetAttribute(moe_gemm<false>,
                         cudaFuncAttributeMaxDynamicSharedMemorySize, SMEM_BYTES);
    cudaFuncSetAttribute(moe_gemm<true>,
                         cudaFuncAttributeMaxDynamicSharedMemorySize, SMEM_BYTES);

    int nsm = 148;
    cudaDeviceGetAttribute(&nsm, cudaDevAttrMultiProcessorCount, 0);

    prep_kernel<<<2049, 256>>>(fi, W1, W2);
    moe_gemm<false><<<nsm, 256, SMEM_BYTES>>>(x, nullptr);
    moe_gemm<true ><<<nsm, 256, SMEM_BYTES>>>(x, fwt);
    combine_kernel<<<(T_TOK * DIM / 4) / 256, 256>>>(out);
}

// round 4
// speedup vs baseline: 3.0984x; 1.9365x over previous
#include <cuda_runtime.h>
#include <cuda_fp16.h>
#include <cstdint>

#define T_TOK 8192
#define DIM   1024
#define NEXP  8
#define NPAIR (T_TOK * 2)

#define BM 128
#define BN 128
#define BK 64                     // halves per chunk -> 128B rows (SW128)
#define NC (DIM / BK)             // 16 chunks
#define STAGES 3
#define TILE_B  (BM * 128)        // 16384 bytes per operand tile chunk
#define STAGE_B (2 * TILE_B)      // 32768
#define SMEM_BYTES (STAGES * STAGE_B)   // 98304
#define MAXITEMS 1536
#define WELEM (NEXP * DIM * DIM)  // 8M elements per weight tensor

// ---- device scratch (allocation-free) ----
__device__ int    g_off[NEXP + 1];
__device__ int    g_pairs[NPAIR];
__device__ int    g_nwork;
__device__ int    g_items[MAXITEMS];
__device__ __half g_Wh[2 * (size_t)WELEM];     // fp16 W1 | W2 (32 MB)
__device__ __half g_Xh[(size_t)T_TOK * DIM];   // fp16 x (16 MB)
__device__ __half g_Hh[(size_t)NPAIR * DIM];   // fp16 relu(x@W1^T), by slot
__device__ float  g_Y[(size_t)NPAIR * DIM];    // fp32 w*relu(h@W2^T), by pair id

// ---- helpers ----
__device__ __forceinline__ uint32_t smem_u32(const void* p) {
    uint32_t a;
    asm("{ .reg .u64 t; cvta.to.shared.u64 t, %1; cvt.u32.u64 %0, t; }"
        : "=r"(a) : "l"(p));
    return a;
}
__device__ __forceinline__ uint32_t swz(uint32_t off) {
    return off ^ ((off >> 3) & 0x70);            // SW128: bits[6:4] ^= bits[9:7]
}
#define CP16(dst, src) \
    asm volatile("cp.async.cg.shared.global [%0], [%1], 16;" :: "r"(dst), "l"(src))
#define CP_COMMIT() asm volatile("cp.async.commit_group;" ::: "memory")
#define CP_WAIT(n)  asm volatile("cp.async.wait_group %0;" :: "n"(n) : "memory")
#define LDM_X4(r, addr) \
    asm volatile("ldmatrix.sync.aligned.m8n8.x4.shared.b16 {%0,%1,%2,%3}, [%4];" \
                 : "=r"((r)[0]), "=r"((r)[1]), "=r"((r)[2]), "=r"((r)[3]) \
                 : "r"(addr))

__device__ __forceinline__ void mma_f16(float* c, const uint32_t* a,
                                        uint32_t b0, uint32_t b1) {
    asm volatile(
        "mma.sync.aligned.m16n8k16.row.col.f32.f16.f16.f32 "
        "{%0,%1,%2,%3}, {%4,%5,%6,%7}, {%8,%9}, {%0,%1,%2,%3};"
        : "+f"(c[0]), "+f"(c[1]), "+f"(c[2]), "+f"(c[3])
        : "r"(a[0]), "r"(a[1]), "r"(a[2]), "r"(a[3]), "r"(b0), "r"(b1));
}

// ---------------------------------------------------------------------------
// Prep: blocks [0,3072) convert X|W1|W2 to fp16 (6M float4 exactly);
// block 3072 does routing + work-list build.
// ---------------------------------------------------------------------------
__global__ void prep_kernel(const int* __restrict__ idx,
                            const float* __restrict__ x,
                            const float* __restrict__ W1,
                            const float* __restrict__ W2) {
    const int tid = threadIdx.x;
    if (blockIdx.x < 3072) {
#pragma unroll
        for (int j = 0; j < 8; j++) {
            size_t v = (size_t)blockIdx.x * 2048 + j * 256 + tid;  // float4 idx
            const float4* s4;
            __half2* d2;
            if (v < 2097152) {                 // X: 2M float4
                s4 = (const float4*)x + v;
                d2 = (__half2*)g_Xh + v * 2;
            } else if (v < 4194304) {          // W1
                size_t u = v - 2097152;
                s4 = (const float4*)W1 + u;
                d2 = (__half2*)g_Wh + u * 2;
            } else {                           // W2
                size_t u = v - 4194304;
                s4 = (const float4*)W2 + u;
                d2 = (__half2*)(g_Wh + WELEM) + u * 2;
            }
            float4 f = *s4;
            d2[0] = __floats2half2_rn(f.x, f.y);
            d2[1] = __floats2half2_rn(f.z, f.w);
        }
        return;
    }
    // ---- routing block ----
    __shared__ int hist[NEXP];
    __shared__ int cur[NEXP];
    if (tid < NEXP) hist[tid] = 0;
    __syncthreads();
    for (int p = tid; p < NPAIR; p += 256) atomicAdd(&hist[idx[p]], 1);
    __syncthreads();
    if (tid == 0) {
        int acc = 0, nw = 0;
        for (int e = 0; e < NEXP; e++) {
            g_off[e] = acc;
            cur[e]   = acc;
            int mt = (hist[e] + BM - 1) / BM;
            for (int m = 0; m < mt; m++)
                for (int n = 0; n < DIM / BN; n++)
                    g_items[nw++] = e | (m << 4) | (n << 12);
            acc += hist[e];
        }
        g_off[NEXP] = acc;
        g_nwork = nw;
    }
    __syncthreads();
    for (int p = tid; p < NPAIR; p += 256)
        g_pairs[atomicAdd(&cur[idx[p]], 1)] = p;
}

// ---------------------------------------------------------------------------
// Persistent grouped GEMM, fp16 mma.sync m16n8k16, ldmatrix frags.
// C[i,j] = sum_k A[i,k] * W[e][j,k]
// FC1: A = gathered x rows (fp16)  -> g_Hh[slot] = fp16(relu(C))
// FC2: A = g_Hh rows               -> g_Y[pair]  = fw*relu(C)   (fp32)
// ---------------------------------------------------------------------------
template <bool FC2>
__global__ __launch_bounds__(256, 2)
void moe_gemm(const float* __restrict__ fw)
{
    extern __shared__ char smem[];
    const uint32_t sbase = smem_u32(smem);
    const int tid  = threadIdx.x;
    const int wid  = tid >> 5;
    const int lane = tid & 31;
    const int g = lane >> 2;
    const int t = lane & 3;
    const int wm = wid & 3;           // warp m (4 x 32 rows)
    const int wn = wid >> 2;          // warp n (2 x 64 cols)

    // loader: thread covers one 128B row of A (tid<128) or B (tid>=128)
    const int lrow  = tid & 127;
    const int lside = tid >> 7;
    uint32_t ldst[8];
#pragma unroll
    for (int j = 0; j < 8; j++)
        ldst[j] = (uint32_t)lside * TILE_B + swz((uint32_t)lrow * 128 + j * 16);

    // ldmatrix lane geometry
    const int lr = (lane & 7) + ((lane >> 3) & 1) * 8;  // row within 16-block
    const int lk = lane >> 4;                            // k-half (16B) select

    const __half* Wb = g_Wh + (FC2 ? (size_t)WELEM : 0);
    const int nwork = g_nwork;

    for (int w = blockIdx.x; w < nwork; w += gridDim.x) {
        const int item = g_items[w];
        const int e  = item & 15;
        const int mt = (item >> 4) & 255;
        const int nt = (item >> 12) & 15;
        const int rowEnd = g_off[e + 1];
        const int row0   = g_off[e] + mt * BM;
        const int n0     = nt * BN;

        // this thread's global source row
        const __half* gsrc;
        if (lside == 0) {
            const int s = min(row0 + lrow, rowEnd - 1);
            if constexpr (FC2) gsrc = g_Hh + (size_t)s * DIM;
            else               gsrc = g_Xh + (size_t)(g_pairs[s] >> 1) * DIM;
        } else {
            gsrc = Wb + ((size_t)e * DIM + n0 + lrow) * DIM;
        }

        auto issue = [&](int c) {
            uint32_t sb = sbase + (uint32_t)(c % STAGES) * STAGE_B;
            const __half* src = gsrc + c * BK;
#pragma unroll
            for (int j = 0; j < 8; j++)
                CP16(sb + ldst[j], src + j * 8);
            CP_COMMIT();
        };

        float acc[2][8][4];
#pragma unroll
        for (int mi = 0; mi < 2; mi++)
#pragma unroll
            for (int nj = 0; nj < 8; nj++)
#pragma unroll
                for (int q = 0; q < 4; q++) acc[mi][nj][q] = 0.f;

        __syncthreads();            // ring safe vs previous tile's consumers
        issue(0);
        issue(1);

        for (int c = 0; c < NC; c++) {
            if (c < NC - 1) CP_WAIT(1); else CP_WAIT(0);
            __syncthreads();        // chunk c visible; all done with chunk c-1
            if (c + 2 < NC) issue(c + 2);

            const uint32_t At = sbase + (uint32_t)(c % STAGES) * STAGE_B;
            const uint32_t Bt = At + TILE_B;
#pragma unroll
            for (int ks = 0; ks < 4; ks++) {
                const uint32_t kseg = (uint32_t)(ks * 2 + lk) * 16;
                uint32_t a[2][4];
#pragma unroll
                for (int mi = 0; mi < 2; mi++)
                    LDM_X4(a[mi], At + swz((uint32_t)(wm * 32 + mi * 16 + lr) * 128 + kseg));
                uint32_t b[4][4];
#pragma unroll
                for (int p = 0; p < 4; p++)
                    LDM_X4(b[p], Bt + swz((uint32_t)(wn * 64 + p * 16 + lr) * 128 + kseg));
#pragma unroll
                for (int mi = 0; mi < 2; mi++)
#pragma unroll
                    for (int p = 0; p < 4; p++) {
                        mma_f16(acc[mi][2 * p + 0], a[mi], b[p][0], b[p][2]);
                        mma_f16(acc[mi][2 * p + 1], a[mi], b[p][1], b[p][3]);
                    }
            }
        }

        // epilogue: thread owns rows wm*32+mi*16+h*8+g, cols wn*64+nj*8+2t
#pragma unroll
        for (int mi = 0; mi < 2; mi++)
#pragma unroll
            for (int h = 0; h < 2; h++) {
                const int sr = row0 + wm * 32 + mi * 16 + h * 8 + g;
                if (sr >= rowEnd) continue;
                if constexpr (FC2) {
                    const int p = g_pairs[sr];
                    const float wsc = fw[p];
                    float* dst = g_Y + (size_t)p * DIM + n0;
#pragma unroll
                    for (int nj = 0; nj < 8; nj++) {
                        const int col = wn * 64 + nj * 8 + 2 * t;
                        float2 o;
                        o.x = fmaxf(acc[mi][nj][h * 2 + 0], 0.f) * wsc;
                        o.y = fmaxf(acc[mi][nj][h * 2 + 1], 0.f) * wsc;
                        *(float2*)(dst + col) = o;
                    }
                } else {
                    __half* dst = g_Hh + (size_t)sr * DIM + n0;
#pragma unroll
                    for (int nj = 0; nj < 8; nj++) {
                        const int col = wn * 64 + nj * 8 + 2 * t;
                        float v0 = fmaxf(acc[mi][nj][h * 2 + 0], 0.f);
                        float v1 = fmaxf(acc[mi][nj][h * 2 + 1], 0.f);
                        *(__half2*)(dst + col) = __floats2half2_rn(v0, v1);
                    }
                }
            }
    }
}

// ---------------------------------------------------------------------------
// Combine: out[t] = Y[2t] + Y[2t+1]  (K = 2), coalesced, deterministic.
// ---------------------------------------------------------------------------
__global__ void combine_kernel(float* __restrict__ out) {
    const int i = blockIdx.x * blockDim.x + threadIdx.x;   // T*D/4 elements
    const float4* Y = (const float4*)g_Y;
    const int tk = i >> 8;            // token (256 float4 per row)
    const int rem = i & 255;
    float4 a = Y[(size_t)tk * 512 + rem];
    float4 b = Y[(size_t)tk * 512 + 256 + rem];
    float4 o;
    o.x = a.x + b.x; o.y = a.y + b.y; o.z = a.z + b.z; o.w = a.w + b.w;
    ((float4*)out)[i] = o;
}

// ---------------------------------------------------------------------------
extern "C" void kernel_launch(void* const* d_in, const int* in_sizes, int n_in,
                              void* d_out, int out_size) {
    const float* x   = (const float*)d_in[0];
    const int*   fi  = (const int*)d_in[1];
    const float* fwt = (const float*)d_in[2];
    const float* W1  = (const float*)d_in[3];
    const float* W2  = (const float*)d_in[4];
    float* out = (float*)d_out;

    cudaFuncSetAttribute(moe_gemm<false>,
                         cudaFuncAttributeMaxDynamicSharedMemorySize, SMEM_BYTES);
    cudaFuncSetAttribute(moe_gemm<true>,
                         cudaFuncAttributeMaxDynamicSharedMemorySize, SMEM_BYTES);

    int nsm = 148;
    cudaDeviceGetAttribute(&nsm, cudaDevAttrMultiProcessorCount, 0);

    prep_kernel<<<3073, 256>>>(fi, x, W1, W2);
    moe_gemm<false><<<2 * nsm, 256, SMEM_BYTES>>>(nullptr);
    moe_gemm<true ><<<2 * nsm, 256, SMEM_BYTES>>>(fwt);
    combine_kernel<<<(T_TOK * DIM / 4) / 256, 256>>>(out);
}